// round 8
// baseline (speedup 1.0000x reference)
#include <cuda_runtime.h>
#include <math.h>

#define KC 8
#define LV 8
#define TS (1u << 18)
#define FF 2
#define HID 64
#define ENC (LV * FF)              // 16
#define W1_STRIDE (ENC * HID + 4)  // 1028 floats: +4 skews banks per cluster
#define NT 256
#define NPTS 524288
#define SORT_RES 32
#define NBINS (SORT_RES * SORT_RES * SORT_RES)   // 32768

__device__ unsigned d_bins[NBINS];
__device__ unsigned d_offs[NBINS];
__device__ float4   d_spos[NPTS];   // x, y, z, bitcast(origidx)

__device__ __forceinline__ unsigned cell_key(float x, float y, float z)
{
    unsigned cx = min((unsigned)(x * (float)SORT_RES), SORT_RES - 1u);
    unsigned cy = min((unsigned)(y * (float)SORT_RES), SORT_RES - 1u);
    unsigned cz = min((unsigned)(z * (float)SORT_RES), SORT_RES - 1u);
    return cx | (cy << 5) | (cz << 10);
}

__global__ void k_zero()
{
    int i = blockIdx.x * blockDim.x + threadIdx.x;
    if (i < NBINS) d_bins[i] = 0;
}

// 4 points per thread, vectorized float4 position loads (12 floats = 3 float4).
__global__ void k_count(const float4* __restrict__ pos4, int N4)
{
    int t = blockIdx.x * blockDim.x + threadIdx.x;
    if (t >= N4) return;
    float4 a = __ldg(&pos4[t * 3 + 0]);
    float4 b = __ldg(&pos4[t * 3 + 1]);
    float4 c = __ldg(&pos4[t * 3 + 2]);
    atomicAdd(&d_bins[cell_key(a.x, a.y, a.z)], 1u);
    atomicAdd(&d_bins[cell_key(a.w, b.x, b.y)], 1u);
    atomicAdd(&d_bins[cell_key(b.z, b.w, c.x)], 1u);
    atomicAdd(&d_bins[cell_key(c.y, c.z, c.w)], 1u);
}

__global__ __launch_bounds__(1024) void k_scan()
{
    __shared__ unsigned ssum[1024];
    const int t = threadIdx.x;
    unsigned loc[NBINS / 1024];
    unsigned s = 0;
#pragma unroll
    for (int i = 0; i < NBINS / 1024; i++) {
        loc[i] = d_bins[t * (NBINS / 1024) + i];
        s += loc[i];
    }
    ssum[t] = s;
    __syncthreads();
    for (int off = 1; off < 1024; off <<= 1) {
        unsigned v = (t >= off) ? ssum[t - off] : 0u;
        __syncthreads();
        ssum[t] += v;
        __syncthreads();
    }
    unsigned ex = (t == 0) ? 0u : ssum[t - 1];
#pragma unroll
    for (int i = 0; i < NBINS / 1024; i++) {
        unsigned c = loc[i];
        d_offs[t * (NBINS / 1024) + i] = ex;
        ex += c;
    }
}

// 1 point per thread for maximum TLP; packed float4 scattered store.
__global__ void k_scatter(const float* __restrict__ positions, int N)
{
    int i = blockIdx.x * blockDim.x + threadIdx.x;
    if (i >= N) return;
    float x = positions[i * 3 + 0];
    float y = positions[i * 3 + 1];
    float z = positions[i * 3 + 2];
    unsigned slot = atomicAdd(&d_offs[cell_key(x, y, z)], 1u);
    d_spos[slot] = make_float4(x, y, z, __int_as_float(i));
}

__global__ __launch_bounds__(NT, 5)
void density_kernel(const float* __restrict__ centroids,
                    const float* __restrict__ tables,
                    const float* __restrict__ W1,
                    const float* __restrict__ b1,
                    const float* __restrict__ W2,
                    const float* __restrict__ b2,
                    float* __restrict__ out, int N)
{
    __shared__ float sW1[KC * W1_STRIDE];
    __shared__ float sb1[KC * HID];
    __shared__ float sW2[KC * HID];
    __shared__ float sb2[KC];
    __shared__ float sc[KC * 3];

    const int tid = threadIdx.x;

    for (int i = tid; i < KC * ENC * HID; i += NT) {
        int k = i / (ENC * HID);
        int r = i - k * (ENC * HID);
        sW1[k * W1_STRIDE + r] = W1[i];
    }
    for (int i = tid; i < KC * HID; i += NT) {
        sb1[i] = b1[i];
        sW2[i] = W2[i];
    }
    if (tid < KC) sb2[tid] = b2[tid];
    if (tid < KC * 3) sc[tid] = centroids[tid];
    __syncthreads();

    const int idx = blockIdx.x * NT + tid;
    if (idx >= N) return;

    const float4 p = d_spos[idx];
    const float px = p.x, py = p.y, pz = p.z;
    const int oidx = __float_as_int(p.w);

    // --- nearest centroid (first-min tie break, matches argmin) ---
    int kbest = 0;
    float dbest = 3.4e38f;
#pragma unroll
    for (int k = 0; k < KC; k++) {
        float dx = px - sc[k * 3 + 0];
        float dy = py - sc[k * 3 + 1];
        float dz = pz - sc[k * 3 + 2];
        float d = dx * dx + dy * dy + dz * dz;
        if (d < dbest) { dbest = d; kbest = k; }
    }

    // --- multi-resolution hash encoding (branch-free corner pairing) ---
    float enc[ENC];
    const float2* tbl = reinterpret_cast<const float2*>(tables);
    const unsigned kbase = (unsigned)kbest * LV;

    float res = 16.0f;
#pragma unroll
    for (int l = 0; l < LV; l++) {
        const float sx = px * res, sy = py * res, sz = pz * res;
        const float fx = floorf(sx), fy = floorf(sy), fz = floorf(sz);
        const float wx = sx - fx, wy = sy - fy, wz = sz - fz;
        const unsigned x0 = (unsigned)fx, y0 = (unsigned)fy, z0 = (unsigned)fz;
        const unsigned hy0 = y0 * 2654435761u, hy1 = (y0 + 1u) * 2654435761u;
        const unsigned hz0 = z0 * 805459861u,  hz1 = (z0 + 1u) * 805459861u;
        const unsigned lbase = (kbase + (unsigned)l) * TS;
        const unsigned hxor = x0 ^ (x0 + 1u);   // =1 iff x0 even
        const bool xodd = (x0 & 1u) != 0u;

        float e0 = 0.0f, e1 = 0.0f;
#pragma unroll
        for (int c = 0; c < 4; c++) {        // c bit1 = y, bit0 = z
            const unsigned hy = (c & 2) ? hy1 : hy0;
            const unsigned hz = (c & 1) ? hz1 : hz0;
            const unsigned h0 = (x0 ^ hy ^ hz) & (TS - 1u);

            // Aligned float4 always holds corner-0's float2 (and, when x0
            // is even, also corner-1's, since then h1 = h0^1).
            const float4 q = __ldg(reinterpret_cast<const float4*>(
                tbl + lbase + (h0 & ~1u)));
            const bool hi = (h0 & 1u) != 0u;
            float2 f0, f1;
            f0.x = hi ? q.z : q.x;  f0.y = hi ? q.w : q.y;
            f1.x = hi ? q.x : q.z;  f1.y = hi ? q.y : q.w;
            if (xodd) {   // one-armed predicated load, no BSSY
                f1 = __ldg(&tbl[lbase + (h0 ^ hxor)]);
            }

            const float cwy = (c & 2) ? wy : 1.0f - wy;
            const float cwz = (c & 1) ? wz : 1.0f - wz;
            const float cwyz = cwy * cwz;
            const float cw0 = (1.0f - wx) * cwyz;
            const float cw1 = wx * cwyz;
            e0 = fmaf(f0.x, cw0, fmaf(f1.x, cw1, e0));
            e1 = fmaf(f0.y, cw0, fmaf(f1.y, cw1, e1));
        }
        enc[2 * l + 0] = e0;
        enc[2 * l + 1] = e1;
        res *= 2.0f;
    }

    // --- per-cluster MLP (sorted order -> kbest nearly warp-uniform) ---
    const float* w1k = sW1 + kbest * W1_STRIDE;
    const float* b1k = sb1 + kbest * HID;
    const float* w2k = sW2 + kbest * HID;
    float dens = sb2[kbest];

#pragma unroll
    for (int jc = 0; jc < HID / 16; jc++) {
        float4 h4[4];
#pragma unroll
        for (int q = 0; q < 4; q++)
            h4[q] = *reinterpret_cast<const float4*>(b1k + jc * 16 + q * 4);
#pragma unroll
        for (int i = 0; i < ENC; i++) {
            const float e = enc[i];
#pragma unroll
            for (int q = 0; q < 4; q++) {
                const float4 w = *reinterpret_cast<const float4*>(
                    w1k + i * HID + jc * 16 + q * 4);
                h4[q].x = fmaf(e, w.x, h4[q].x);
                h4[q].y = fmaf(e, w.y, h4[q].y);
                h4[q].z = fmaf(e, w.z, h4[q].z);
                h4[q].w = fmaf(e, w.w, h4[q].w);
            }
        }
#pragma unroll
        for (int q = 0; q < 4; q++) {
            const float4 w2 = *reinterpret_cast<const float4*>(w2k + jc * 16 + q * 4);
            dens = fmaf(fmaxf(h4[q].x, 0.0f), w2.x, dens);
            dens = fmaf(fmaxf(h4[q].y, 0.0f), w2.y, dens);
            dens = fmaf(fmaxf(h4[q].z, 0.0f), w2.z, dens);
            dens = fmaf(fmaxf(h4[q].w, 0.0f), w2.w, dens);
        }
    }

    out[oidx] = __expf(dens);
}

extern "C" void kernel_launch(void* const* d_in, const int* in_sizes, int n_in,
                              void* d_out, int out_size)
{
    const float* positions = (const float*)d_in[0];
    const float* centroids = (const float*)d_in[1];
    const float* tables    = (const float*)d_in[2];
    const float* W1        = (const float*)d_in[3];
    const float* b1        = (const float*)d_in[4];
    const float* W2        = (const float*)d_in[5];
    const float* b2        = (const float*)d_in[6];
    float* out = (float*)d_out;

    const int N = in_sizes[0] / 3;
    const int N4 = N / 4;   // N = 524288, divisible by 4

    k_zero<<<(NBINS + 255) / 256, 256>>>();
    k_count<<<(N4 + 255) / 256, 256>>>((const float4*)positions, N4);
    k_scan<<<1, 1024>>>();
    k_scatter<<<(N + 255) / 256, 256>>>(positions, N);
    density_kernel<<<(N + NT - 1) / NT, NT>>>(centroids, tables,
                                              W1, b1, W2, b2, out, N);
}

// round 9
// speedup vs baseline: 1.3319x; 1.3319x over previous
#include <cuda_runtime.h>
#include <math.h>

#define KC 8
#define LV 8
#define TS (1u << 18)
#define FF 2
#define HID 64
#define ENC (LV * FF)              // 16
#define W1_STRIDE (ENC * HID + 4)  // 1028 floats: +4 skews banks per cluster
#define NT 256
#define NPTS 524288
#define SORT_RES 64
#define NBINS (SORT_RES * SORT_RES * SORT_RES)   // 262144
#define NPART 1024                               // NBINS / 256

__device__ unsigned d_bins[NBINS];
__device__ unsigned d_offs[NBINS];
__device__ unsigned d_part[NPART];
__device__ float4   d_spos[NPTS];   // x, y, z, bitcast(origidx)

__device__ __forceinline__ unsigned cell_key(float x, float y, float z)
{
    unsigned cx = min((unsigned)(x * (float)SORT_RES), SORT_RES - 1u);
    unsigned cy = min((unsigned)(y * (float)SORT_RES), SORT_RES - 1u);
    unsigned cz = min((unsigned)(z * (float)SORT_RES), SORT_RES - 1u);
    return cx | (cy << 6) | (cz << 12);   // x fastest: hash-contiguity in x
}

__global__ void k_zero()
{
    int i = blockIdx.x * blockDim.x + threadIdx.x;
    if (i < NBINS) d_bins[i] = 0;
}

// 4 points per thread, vectorized float4 position loads.
__global__ void k_count(const float4* __restrict__ pos4, int N4)
{
    int t = blockIdx.x * blockDim.x + threadIdx.x;
    if (t >= N4) return;
    float4 a = __ldg(&pos4[t * 3 + 0]);
    float4 b = __ldg(&pos4[t * 3 + 1]);
    float4 c = __ldg(&pos4[t * 3 + 2]);
    atomicAdd(&d_bins[cell_key(a.x, a.y, a.z)], 1u);
    atomicAdd(&d_bins[cell_key(a.w, b.x, b.y)], 1u);
    atomicAdd(&d_bins[cell_key(b.z, b.w, c.x)], 1u);
    atomicAdd(&d_bins[cell_key(c.y, c.z, c.w)], 1u);
}

// Stage A: per-block (256-bin) sums.
__global__ __launch_bounds__(256) void k_scan_a()
{
    __shared__ unsigned s[256];
    const int t = threadIdx.x;
    s[t] = d_bins[blockIdx.x * 256 + t];
    __syncthreads();
#pragma unroll
    for (int off = 128; off > 0; off >>= 1) {
        if (t < off) s[t] += s[t + off];
        __syncthreads();
    }
    if (t == 0) d_part[blockIdx.x] = s[0];
}

// Stage B: exclusive scan of the 1024 partials (single block).
__global__ __launch_bounds__(1024) void k_scan_b()
{
    __shared__ unsigned s[1024];
    const int t = threadIdx.x;
    unsigned v = d_part[t];
    s[t] = v;
    __syncthreads();
    for (int off = 1; off < 1024; off <<= 1) {
        unsigned u = (t >= off) ? s[t - off] : 0u;
        __syncthreads();
        s[t] += u;
        __syncthreads();
    }
    d_part[t] = s[t] - v;   // exclusive
}

// Stage C: per-block exclusive scan of 256 bins + block base -> d_offs.
__global__ __launch_bounds__(256) void k_scan_c()
{
    __shared__ unsigned s[256];
    const int t = threadIdx.x;
    unsigned v = d_bins[blockIdx.x * 256 + t];
    s[t] = v;
    __syncthreads();
    for (int off = 1; off < 256; off <<= 1) {
        unsigned u = (t >= off) ? s[t - off] : 0u;
        __syncthreads();
        s[t] += u;
        __syncthreads();
    }
    d_offs[blockIdx.x * 256 + t] = s[t] - v + d_part[blockIdx.x];
}

__global__ void k_scatter(const float* __restrict__ positions, int N)
{
    int i = blockIdx.x * blockDim.x + threadIdx.x;
    if (i >= N) return;
    float x = positions[i * 3 + 0];
    float y = positions[i * 3 + 1];
    float z = positions[i * 3 + 2];
    unsigned slot = atomicAdd(&d_offs[cell_key(x, y, z)], 1u);
    d_spos[slot] = make_float4(x, y, z, __int_as_float(i));
}

__global__ __launch_bounds__(NT, 5)
void density_kernel(const float* __restrict__ centroids,
                    const float* __restrict__ tables,
                    const float* __restrict__ W1,
                    const float* __restrict__ b1,
                    const float* __restrict__ W2,
                    const float* __restrict__ b2,
                    float* __restrict__ out, int N)
{
    __shared__ float sW1[KC * W1_STRIDE];
    __shared__ float sb1[KC * HID];
    __shared__ float sW2[KC * HID];
    __shared__ float sb2[KC];
    __shared__ float sc[KC * 3];

    const int tid = threadIdx.x;

    for (int i = tid; i < KC * ENC * HID; i += NT) {
        int k = i / (ENC * HID);
        int r = i - k * (ENC * HID);
        sW1[k * W1_STRIDE + r] = W1[i];
    }
    for (int i = tid; i < KC * HID; i += NT) {
        sb1[i] = b1[i];
        sW2[i] = W2[i];
    }
    if (tid < KC) sb2[tid] = b2[tid];
    if (tid < KC * 3) sc[tid] = centroids[tid];
    __syncthreads();

    const int idx = blockIdx.x * NT + tid;
    if (idx >= N) return;

    const float4 p = d_spos[idx];
    const float px = p.x, py = p.y, pz = p.z;
    const int oidx = __float_as_int(p.w);

    // --- nearest centroid (first-min tie break, matches argmin) ---
    int kbest = 0;
    float dbest = 3.4e38f;
#pragma unroll
    for (int k = 0; k < KC; k++) {
        float dx = px - sc[k * 3 + 0];
        float dy = py - sc[k * 3 + 1];
        float dz = pz - sc[k * 3 + 2];
        float d = dx * dx + dy * dy + dz * dz;
        if (d < dbest) { dbest = d; kbest = k; }
    }

    // --- multi-resolution hash encoding ---
    float enc[ENC];
    const float2* tbl = reinterpret_cast<const float2*>(tables);
    const unsigned kbase = (unsigned)kbest * LV;

    float res = 16.0f;
#pragma unroll
    for (int l = 0; l < LV; l++) {
        const float sx = px * res, sy = py * res, sz = pz * res;
        const float fx = floorf(sx), fy = floorf(sy), fz = floorf(sz);
        const float wx = sx - fx, wy = sy - fy, wz = sz - fz;
        const unsigned x0 = (unsigned)fx, y0 = (unsigned)fy, z0 = (unsigned)fz;
        const unsigned hy0 = y0 * 2654435761u, hy1 = (y0 + 1u) * 2654435761u;
        const unsigned hz0 = z0 * 805459861u,  hz1 = (z0 + 1u) * 805459861u;
        const unsigned lbase = (kbase + (unsigned)l) * TS;
        const bool xeven = (x0 & 1u) == 0u;
        const unsigned hxor = x0 ^ (x0 + 1u);  // =1 when x0 even

        float e0 = 0.0f, e1 = 0.0f;
#pragma unroll
        for (int c = 0; c < 4; c++) {        // c bit1 = y, bit0 = z
            const unsigned hy = (c & 2) ? hy1 : hy0;
            const unsigned hz = (c & 1) ? hz1 : hz0;
            const unsigned a = (x0 ^ hy ^ hz) & (TS - 1u);

            float2 f0, f1;
            if (xeven) {
                const float4 q = __ldg(reinterpret_cast<const float4*>(
                    tbl + lbase + (a & ~1u)));
                const bool hi = (a & 1u) != 0u;
                f0.x = hi ? q.z : q.x;  f0.y = hi ? q.w : q.y;
                f1.x = hi ? q.x : q.z;  f1.y = hi ? q.y : q.w;
            } else {
                f0 = __ldg(&tbl[lbase + a]);
                f1 = __ldg(&tbl[lbase + (a ^ hxor)]);
            }

            const float cwy = (c & 2) ? wy : 1.0f - wy;
            const float cwz = (c & 1) ? wz : 1.0f - wz;
            const float cwyz = cwy * cwz;
            const float cw0 = (1.0f - wx) * cwyz;
            const float cw1 = wx * cwyz;
            e0 = fmaf(f0.x, cw0, fmaf(f1.x, cw1, e0));
            e1 = fmaf(f0.y, cw0, fmaf(f1.y, cw1, e1));
        }
        enc[2 * l + 0] = e0;
        enc[2 * l + 1] = e1;
        res *= 2.0f;
    }

    // --- per-cluster MLP (sorted order -> kbest nearly warp-uniform) ---
    const float* w1k = sW1 + kbest * W1_STRIDE;
    const float* b1k = sb1 + kbest * HID;
    const float* w2k = sW2 + kbest * HID;
    float dens = sb2[kbest];

#pragma unroll
    for (int jc = 0; jc < HID / 16; jc++) {
        float4 h4[4];
#pragma unroll
        for (int q = 0; q < 4; q++)
            h4[q] = *reinterpret_cast<const float4*>(b1k + jc * 16 + q * 4);
#pragma unroll
        for (int i = 0; i < ENC; i++) {
            const float e = enc[i];
#pragma unroll
            for (int q = 0; q < 4; q++) {
                const float4 w = *reinterpret_cast<const float4*>(
                    w1k + i * HID + jc * 16 + q * 4);
                h4[q].x = fmaf(e, w.x, h4[q].x);
                h4[q].y = fmaf(e, w.y, h4[q].y);
                h4[q].z = fmaf(e, w.z, h4[q].z);
                h4[q].w = fmaf(e, w.w, h4[q].w);
            }
        }
#pragma unroll
        for (int q = 0; q < 4; q++) {
            const float4 w2 = *reinterpret_cast<const float4*>(w2k + jc * 16 + q * 4);
            dens = fmaf(fmaxf(h4[q].x, 0.0f), w2.x, dens);
            dens = fmaf(fmaxf(h4[q].y, 0.0f), w2.y, dens);
            dens = fmaf(fmaxf(h4[q].z, 0.0f), w2.z, dens);
            dens = fmaf(fmaxf(h4[q].w, 0.0f), w2.w, dens);
        }
    }

    out[oidx] = __expf(dens);
}

extern "C" void kernel_launch(void* const* d_in, const int* in_sizes, int n_in,
                              void* d_out, int out_size)
{
    const float* positions = (const float*)d_in[0];
    const float* centroids = (const float*)d_in[1];
    const float* tables    = (const float*)d_in[2];
    const float* W1        = (const float*)d_in[3];
    const float* b1        = (const float*)d_in[4];
    const float* W2        = (const float*)d_in[5];
    const float* b2        = (const float*)d_in[6];
    float* out = (float*)d_out;

    const int N = in_sizes[0] / 3;
    const int N4 = N / 4;   // N = 524288, divisible by 4

    k_zero<<<(NBINS + 255) / 256, 256>>>();
    k_count<<<(N4 + 255) / 256, 256>>>((const float4*)positions, N4);
    k_scan_a<<<NPART, 256>>>();
    k_scan_b<<<1, 1024>>>();
    k_scan_c<<<NPART, 256>>>();
    k_scatter<<<(N + 255) / 256, 256>>>(positions, N);
    density_kernel<<<(N + NT - 1) / NT, NT>>>(centroids, tables,
                                              W1, b1, W2, b2, out, N);
}